// round 9
// baseline (speedup 1.0000x reference)
#include <cuda_runtime.h>
#include <cuda_bf16.h>
#include <cstdint>

typedef unsigned int uint;

#define NB      1024
#define NIT     100000
#define NCL     10
#define DD      64
#define CH      128                  // items per chunk
#define NCH     782                  // NP / CH
#define NP      (NCH*CH)             // 100096
#define NS      36                   // item splits (contiguous ranges)
#define CPS     22                   // chunks per CTA (ceil 782/36)
#define BT      128                  // batch rows per CTA
#define NSC     98                   // sort CTAs
#define SSPAN   1024
#define LOG2E   1.4426950408889634f

// kmain smem (relative to 1024-aligned base): Ah@0 (16K) | B0@16K B1@32K
#define SM_AH   0
#define SM_B0   16384
#define SMEM_KM (49152 + 1024)

// ---------------- device scratch (zero at load; kmain-fin restores) --------
__device__ float  g_G1[NCL*DD];
__device__ float  g_sums[NB*NCL];
__device__ float  g_cntf[NCL];
__device__ int    g_hist[NSC*NCL];
__device__ int    g_coff[NCL+1];
__device__ int    g_dst[NIT];
__device__ int    g_c1;              // hist-done counter
__device__ int    g_c2;              // kmain-done counter
__device__ __align__(16) unsigned short g_W2h[(size_t)NP*DD];   // padding rows stay 0 forever

// ---------------- PTX helpers (sm_80-class baseline ISA) --------------------
__device__ __forceinline__ uint32_t smem_u32(const void* p) {
    uint32_t a;
    asm("{ .reg .u64 t; cvta.to.shared.u64 t, %1; cvt.u32.u64 %0, t; }" : "=r"(a) : "l"(p));
    return a;
}
__device__ __forceinline__ float ex2f(float x) {
    float r; asm("ex2.approx.ftz.f32 %0, %1;" : "=f"(r) : "f"(x)); return r;
}
#define SW128(o) ((o) ^ (((o) >> 3) & 0x70))

__device__ __forceinline__ void cpa16(uint32_t dst, const void* src) {
    asm volatile("cp.async.cg.shared.global [%0], [%1], 16;" :: "r"(dst), "l"(src));
}
#define CPA_COMMIT() asm volatile("cp.async.commit_group;")
#define CPA_WAIT0()  asm volatile("cp.async.wait_group 0;" ::: "memory")
#define CPA_WAIT1()  asm volatile("cp.async.wait_group 1;" ::: "memory")

#define LDSM4(R, A) \
    asm volatile("ldmatrix.sync.aligned.m8n8.x4.shared.b16 {%0,%1,%2,%3}, [%4];" \
        : "=r"((R)[0]), "=r"((R)[1]), "=r"((R)[2]), "=r"((R)[3]) : "r"(A))

__device__ __forceinline__ void mma_bf16(float* c, const uint* a, uint b0, uint b1) {
    asm volatile("mma.sync.aligned.m16n8k16.row.col.f32.bf16.bf16.f32 "
        "{%0,%1,%2,%3}, {%4,%5,%6,%7}, {%8,%9}, {%0,%1,%2,%3};"
        : "+f"(c[0]), "+f"(c[1]), "+f"(c[2]), "+f"(c[3])
        : "r"(a[0]), "r"(a[1]), "r"(a[2]), "r"(a[3]), "r"(b0), "r"(b1));
}

// ===========================================================================
// Kernel 1: khsG — blocks 0..97: hist -> device-sync -> scan -> scatter
//                  blocks 98..353: G1 segment-sum (no waiting)
// Deadlock-free: waiters (98 CTAs, 320 thr, low regs) always fit on chip.
// ===========================================================================
__global__ void __launch_bounds__(320) khsG(const int* __restrict__ cl,
                                            const float* __restrict__ W1) {
    int t = threadIdx.x, lane = t & 31, w = t >> 5;
    if (blockIdx.x >= NSC) {
        // ---- G1 = segment-sum of W1 ----
        if (t >= 256) return;
        int d = t & 63;
        int stripe = (blockIdx.x - NSC)*4 + (t >> 6), ns = 256*4;
        float acc[NCL];
#pragma unroll
        for (int k = 0; k < NCL; k++) acc[k] = 0.0f;
        for (int i = stripe; i < NIT; i += ns) {
            int c = cl[i];
            float w1 = W1[i*DD + d];
#pragma unroll
            for (int k = 0; k < NCL; k++) if (c == k) acc[k] += w1;
        }
#pragma unroll
        for (int k = 0; k < NCL; k++) atomicAdd(&g_G1[k*DD + d], acc[k]);
        return;
    }

    int bid = blockIdx.x;
    // ---- phase 1: histogram of my span ----
    __shared__ int h[NCL];
    if (t < NCL) h[t] = 0;
    __syncthreads();
    int base = bid * SSPAN;
    if (t < 256) {
        int cnt[NCL];
#pragma unroll
        for (int k = 0; k < NCL; k++) cnt[k] = 0;
#pragma unroll
        for (int q = 0; q < 4; q++) {
            int i = base + q*256 + t;
            if (i < NIT) {
                int c = cl[i];
#pragma unroll
                for (int k = 0; k < NCL; k++) if (c == k) cnt[k]++;
            }
        }
#pragma unroll
        for (int k = 0; k < NCL; k++) if (cnt[k]) atomicAdd(&h[k], cnt[k]);
    }
    __syncthreads();
    if (t < NCL) g_hist[bid*NCL + t] = h[t];
    __threadfence();
    __syncthreads();
    if (t == 0) {
        atomicAdd(&g_c1, 1);
        while (atomicCAS(&g_c1, NSC, NSC) != NSC) __nanosleep(128);
    }
    __syncthreads();

    // ---- phase 2: scan (warp per cluster) ----
    __shared__ int run[NCL];
    __shared__ int wc[8][NCL];
    __shared__ int tot_s[NCL], pre_s[NCL];
    if (w < NCL) {
        int c = w, full = 0, pre = 0;
        for (int b = lane; b < NSC; b += 32) {
            int v = g_hist[b*NCL + c];
            full += v;
            if (b < bid) pre += v;
        }
#pragma unroll
        for (int o = 16; o; o >>= 1) {
            full += __shfl_xor_sync(~0u, full, o);
            pre  += __shfl_xor_sync(~0u, pre,  o);
        }
        if (!lane) { tot_s[c] = full; pre_s[c] = pre; }
    }
    __syncthreads();
    if (t == 0) {
        int r = 0;
        for (int k = 0; k < NCL; k++) {
            int o = r; r += tot_s[k];
            run[k] = o + pre_s[k];
            if (bid == 0) { g_coff[k] = o; g_cntf[k] = (float)tot_s[k]; }
        }
        if (bid == 0) g_coff[NCL] = r;
    }
    __syncthreads();

    // ---- phase 3: rank + scatter ----
    unsigned ltm = (1u << lane) - 1u;
    for (int q = 0; q < 4; q++) {
        if (t < 80) ((int*)wc)[t] = 0;
        __syncthreads();
        int i = base + q*256 + t;
        int c = (t < 256 && i < NIT) ? cl[i] : -1;
        unsigned mm = __match_any_sync(0xffffffffu, c);
        int myrank = __popc(mm & ltm);
        if (c >= 0 && myrank == 0) wc[w][c] = __popc(mm);
        __syncthreads();
        if (t < NCL) {
            int k = t, s = run[k];
            for (int ww = 0; ww < 8; ww++) { int tmp = wc[ww][k]; wc[ww][k] = s; s += tmp; }
            run[k] = s;
        }
        __syncthreads();
        if (c >= 0) g_dst[i] = wc[w][c] + myrank;
        __syncthreads();
    }
}

// ===========================================================================
// Kernel 2: kperm — W2 permute/transpose/bf16 only
// ===========================================================================
#define PITCH 264
__global__ void kperm(const float* __restrict__ W2) {
    extern __shared__ unsigned short shh[];
    int t = threadIdx.x;
    int i = blockIdx.x * 256 + t;
#pragma unroll 8
    for (int d = 0; d < DD; d++) {
        float x = (i < NIT) ? W2[(size_t)d*NIT + i] : 0.0f;
        shh[d*PITCH + t] = __bfloat16_as_ushort(__float2bfloat16(x));
    }
    __syncthreads();
    if (i >= NIT) return;
    int dp = g_dst[i];
    uint v[32];
#pragma unroll
    for (int j = 0; j < 32; j++)
        v[j] = (uint)shh[(2*j)*PITCH + t] | ((uint)shh[(2*j+1)*PITCH + t] << 16);
    uint4* dh = (uint4*)(g_W2h + (size_t)dp*DD);
#pragma unroll
    for (int q = 0; q < 8; q++) dh[q] = make_uint4(v[4*q], v[4*q+1], v[4*q+2], v[4*q+3]);
}

// ===========================================================================
// Kernel 3: kmain — H prologue + bf16 HMMA (4x2 warp split) + fused finalize
// warp layout: wr = w&3 (32 rows), wi = w>>2 (64 items)
// ===========================================================================
__device__ __forceinline__ void stage_B(uint32_t sb, int buf, int ch, int t) {
    uint32_t bh = sb + SM_B0 + buf*16384;
    const char* gh = (const char*)g_W2h + (size_t)ch*CH*128;
#pragma unroll
    for (int q = 0; q < 4; q++) {
        int off = (t + q*256) * 16;
        cpa16(bh + SW128(off), gh + off);
    }
}

// MMA for one 16-item quarter: acc[4][4] = {m0n0, m0n1, m1n0, m1n1}
__device__ __forceinline__ void mma_quarter(float (*acc)[4], const uint (*ah)[4],
                                            uint32_t bq, const int* bx) {
#pragma unroll
    for (int j = 0; j < 4; j++)
#pragma unroll
        for (int k = 0; k < 4; k++) acc[j][k] = 0.0f;
#pragma unroll
    for (int ks = 0; ks < 4; ks++) {
        uint r[4];
        LDSM4(r, bq + bx[ks]);
        mma_bf16(acc[0], ah[0*4 + ks], r[0], r[1]);
        mma_bf16(acc[1], ah[0*4 + ks], r[2], r[3]);
        mma_bf16(acc[2], ah[1*4 + ks], r[0], r[1]);
        mma_bf16(acc[3], ah[1*4 + ks], r[2], r[3]);
    }
}

// exp2 + segment accumulate for one 16-item quarter
__device__ __forceinline__ void epi_quarter(const float (*acc)[4], int pq, int bpos,
                                            bool fast, float* s0, float* s1) {
    if (fast) {
        s0[0] += ex2f(acc[0][0]) + ex2f(acc[0][1]) + ex2f(acc[1][0]) + ex2f(acc[1][1]);
        s0[1] += ex2f(acc[0][2]) + ex2f(acc[0][3]) + ex2f(acc[1][2]) + ex2f(acc[1][3]);
        s0[2] += ex2f(acc[2][0]) + ex2f(acc[2][1]) + ex2f(acc[3][0]) + ex2f(acc[3][1]);
        s0[3] += ex2f(acc[2][2]) + ex2f(acc[2][3]) + ex2f(acc[3][2]) + ex2f(acc[3][3]);
    } else {
#pragma unroll
        for (int jm = 0; jm < 2; jm++)
#pragma unroll
            for (int jn = 0; jn < 2; jn++) {
                int j = jm*2 + jn;
                int p = pq + jn*8;
                float e0 = ex2f(acc[j][0]), e1 = ex2f(acc[j][1]);
                float e2 = ex2f(acc[j][2]), e3 = ex2f(acc[j][3]);
                if (p < bpos)          { s0[jm*2]   += e0; }
                else if (p < NIT)      { s1[jm*2]   += e0; }
                if (p + 1 < bpos)      { s0[jm*2]   += e1; }
                else if (p + 1 < NIT)  { s1[jm*2]   += e1; }
                if (p < bpos)          { s0[jm*2+1] += e2; }
                else if (p < NIT)      { s1[jm*2+1] += e2; }
                if (p + 1 < bpos)      { s0[jm*2+1] += e3; }
                else if (p + 1 < NIT)  { s1[jm*2+1] += e3; }
            }
    }
}

__global__ void __launch_bounds__(256, 2) kmain(const float* __restrict__ inp,
                                                float* __restrict__ out) {
    extern __shared__ char dsm[];
    __shared__ int coff_s[NCL+1];
    __shared__ int slast;
    uint32_t sb0 = smem_u32(dsm);
    uint32_t pad = (1024u - (sb0 & 1023u)) & 1023u;
    uint32_t sb  = sb0 + pad;
    char*    bp  = dsm + pad;

    int t = threadIdx.x, lane = t & 31, w = t >> 5;
    int wr = w & 3, wi = w >> 2;
    int bbase = blockIdx.x * BT;
    int ch_lo = blockIdx.y * CPS;
    int ch_hi = min(ch_lo + CPS, NCH);
    int n = ch_hi - ch_lo;

    if (t < NCL+1) coff_s[t] = g_coff[t];

    // ---- prologue: compute H tile (input @ G1)*log2e -> bf16 -> A smem ----
    {
        float* finp = (float*)(bp + SM_B0);          // 1280 f
        float* fg1  = finp + BT*NCL;                 // 640 f
        for (int idx = t; idx < BT*NCL; idx += 256) finp[idx] = inp[bbase*NCL + idx];
        for (int idx = t; idx < NCL*DD; idx += 256) fg1[idx] = g_G1[idx];
        __syncthreads();
        for (int idx = t; idx < BT*DD; idx += 256) {
            int row = idx >> 6, d = idx & 63;
            float a = 0.0f;
#pragma unroll
            for (int c = 0; c < NCL; c++) a += finp[row*NCL + c] * fg1[c*DD + d];
            a *= LOG2E;
            *(unsigned short*)(bp + SM_AH + SW128(row*128 + d*2)) =
                __bfloat16_as_ushort(__float2bfloat16(a));
        }
        __syncthreads();   // scratch consumed, A visible
    }
    stage_B(sb, 0, ch_lo, t);
    CPA_COMMIT();

    // per-lane ldmatrix B address precompute (relative to quarter base)
    int m  = lane >> 3, rl = lane & 7;
    int rowb = ((m >> 1) << 3) + rl;
    int kadd = m & 1;
    int bx[4];
#pragma unroll
    for (int ks = 0; ks < 4; ks++)
        bx[ks] = rowb*128 + ((ks*32 + kadd*16) ^ (rl*16));

    // A fragments: 2 m-tiles x 4 k-steps, resident
    uint ah[8][4];
    {
#pragma unroll
        for (int mt = 0; mt < 2; mt++) {
            int arow = wr*32 + mt*16 + ((lane >> 3) & 1)*8 + rl;
#pragma unroll
            for (int ks = 0; ks < 4; ks++) {
                int au   = ks*2 + (lane >> 4);
                LDSM4(ah[mt*4 + ks], sb + SM_AH + arow*128 + ((au*16) ^ (rl*16)));
            }
        }
    }

    int rbase = bbase + wr*32 + (lane >> 2);   // rows rbase + {0,8,16,24}
    int qd    = (lane & 3) * 2;
    float s0[4] = {0,0,0,0}, s1[4] = {0,0,0,0};
    int cur = 0;
    { int ib = ch_lo * CH; while (coff_s[cur+1] <= ib) cur++; }

    for (int ii = 0; ii < n; ii++) {
        int buf = ii & 1;
        if (ii + 1 < n) { stage_B(sb, buf ^ 1, ch_lo + ii + 1, t); CPA_COMMIT(); CPA_WAIT1(); }
        else            { CPA_WAIT0(); }
        __syncthreads();

        uint32_t bbh = sb + SM_B0 + buf*16384 + wi*4*2048;   // my 64-item half
        int ibase = (ch_lo + ii) * CH;

        // cluster-boundary flush
        {
            int nc = cur;
            while (coff_s[nc+1] <= ibase) nc++;
            if (nc != cur) {
#pragma unroll
                for (int sl = 0; sl < 4; sl++) {
                    atomicAdd(&g_sums[(rbase + sl*8)*NCL + cur], s0[sl]);
                    if (cur + 1 < NCL) atomicAdd(&g_sums[(rbase + sl*8)*NCL + cur + 1], s1[sl]);
                    s0[sl] = 0.f; s1[sl] = 0.f;
                }
                cur = nc;
            }
        }
        int bpos = coff_s[cur+1];
        bool fast = (ibase + CH <= bpos);
        int pq0 = ibase + wi*64 + qd;

        // quarter-pipelined (16 items each): MMA(q) overlaps EPI(q-1)
        float accA[4][4], accB[4][4];
        mma_quarter(accA, (const uint(*)[4])ah, bbh + 0*2048, bx);
        mma_quarter(accB, (const uint(*)[4])ah, bbh + 1*2048, bx);
        epi_quarter(accA, pq0,      bpos, fast, s0, s1);
        mma_quarter(accA, (const uint(*)[4])ah, bbh + 2*2048, bx);
        epi_quarter(accB, pq0 + 16, bpos, fast, s0, s1);
        mma_quarter(accB, (const uint(*)[4])ah, bbh + 3*2048, bx);
        epi_quarter(accA, pq0 + 32, bpos, fast, s0, s1);
        epi_quarter(accB, pq0 + 48, bpos, fast, s0, s1);

        __syncthreads();
    }

#pragma unroll
    for (int sl = 0; sl < 4; sl++) {
        atomicAdd(&g_sums[(rbase + sl*8)*NCL + cur], s0[sl]);
        if (cur + 1 < NCL) atomicAdd(&g_sums[(rbase + sl*8)*NCL + cur + 1], s1[sl]);
    }

    // ---- fused finalize: last CTA computes output + restores zeros ----
    __threadfence();
    __syncthreads();
    if (t == 0) slast = (atomicAdd(&g_c2, 1) == (int)(gridDim.x*gridDim.y) - 1);
    __syncthreads();
    if (slast) {
        __threadfence();
        for (int b = t; b < NB; b += 256) {
            float v[NCL], z = 0.0f;
#pragma unroll
            for (int c = 0; c < NCL; c++) { v[c] = g_sums[b*NCL + c]; z += v[c]; }
            float invz = 1.0f / z;
#pragma unroll
            for (int c = 0; c < NCL; c++)
                out[b*NCL + c] = v[c] * invz / fmaxf(g_cntf[c], 1.0f);
#pragma unroll
            for (int c = 0; c < NCL; c++) g_sums[b*NCL + c] = 0.0f;
        }
        for (int i = t; i < NCL*DD; i += 256) g_G1[i] = 0.0f;
        if (t == 0) { g_c1 = 0; g_c2 = 0; }
    }
}

// ---------------------------------------------------------------------------
extern "C" void kernel_launch(void* const* d_in, const int* in_sizes, int n_in,
                              void* d_out, int out_size) {
    const float* input = (const float*)d_in[0];   // (1024, 10) f32
    const int*   clust = (const int*)d_in[1];     // (100000,) i32
    const float* W1    = (const float*)d_in[2];   // (100000, 64) f32
    const float* W2    = (const float*)d_in[3];   // (64, 100000) f32
    float*       out   = (float*)d_out;           // (1024, 10) f32

    cudaFuncSetAttribute(kmain, cudaFuncAttributeMaxDynamicSharedMemorySize, SMEM_KM);
    cudaFuncSetAttribute(kperm, cudaFuncAttributeMaxDynamicSharedMemorySize, DD*PITCH*2);

    khsG<<<NSC + 256, 320>>>(clust, W1);
    kperm<<<391, 256, DD*PITCH*2>>>(W2);
    dim3 grid(NB / BT, NS);
    kmain<<<grid, 256, SMEM_KM>>>(input, out);
}

// round 10
// speedup vs baseline: 1.1467x; 1.1467x over previous
#include <cuda_runtime.h>
#include <cuda_bf16.h>
#include <cstdint>

typedef unsigned int uint;

#define NB      1024
#define NIT     100000
#define NCL     10
#define DD      64
#define CH      128                  // items per chunk
#define NCH     782                  // NP / CH
#define NP      (NCH*CH)             // 100096
#define NS      36                   // item splits (contiguous ranges)
#define CPS     22                   // chunks per CTA (ceil 782/36)
#define BT      128                  // batch rows per CTA
#define NSC     98                   // sort CTAs
#define SSPAN   1024
#define LOG2E   1.4426950408889634f

// kmain smem (relative to 1024-aligned base): Ah@0 (16K) | B0@16K B1@32K
#define SM_AH   0
#define SM_B0   16384
#define SMEM_KM (49152 + 1024)

// ---------------- device scratch (zero at load; kmain-fin restores) --------
__device__ float  g_G1[NCL*DD];
__device__ float  g_sums[NB*NCL];
__device__ float  g_cntf[NCL];
__device__ int    g_hist[NSC*NCL];
__device__ int    g_coff[NCL+1];
__device__ int    g_dst[NIT];
__device__ int    g_c1;              // hist-done counter
__device__ int    g_c2;              // kmain-done counter
__device__ __align__(16) unsigned short g_W2h[(size_t)NP*DD];   // padding rows stay 0 forever

// ---------------- PTX helpers (sm_80-class baseline ISA) --------------------
__device__ __forceinline__ uint32_t smem_u32(const void* p) {
    uint32_t a;
    asm("{ .reg .u64 t; cvta.to.shared.u64 t, %1; cvt.u32.u64 %0, t; }" : "=r"(a) : "l"(p));
    return a;
}
__device__ __forceinline__ float ex2f(float x) {
    float r; asm("ex2.approx.ftz.f32 %0, %1;" : "=f"(r) : "f"(x)); return r;
}
#define SW128(o) ((o) ^ (((o) >> 3) & 0x70))

__device__ __forceinline__ void cpa16(uint32_t dst, const void* src) {
    asm volatile("cp.async.cg.shared.global [%0], [%1], 16;" :: "r"(dst), "l"(src));
}
#define CPA_COMMIT() asm volatile("cp.async.commit_group;")
#define CPA_WAIT0()  asm volatile("cp.async.wait_group 0;" ::: "memory")
#define CPA_WAIT1()  asm volatile("cp.async.wait_group 1;" ::: "memory")

#define LDSM4(R, A) \
    asm volatile("ldmatrix.sync.aligned.m8n8.x4.shared.b16 {%0,%1,%2,%3}, [%4];" \
        : "=r"((R)[0]), "=r"((R)[1]), "=r"((R)[2]), "=r"((R)[3]) : "r"(A))

__device__ __forceinline__ void mma_bf16(float* c, const uint* a, uint b0, uint b1) {
    asm volatile("mma.sync.aligned.m16n8k16.row.col.f32.bf16.bf16.f32 "
        "{%0,%1,%2,%3}, {%4,%5,%6,%7}, {%8,%9}, {%0,%1,%2,%3};"
        : "+f"(c[0]), "+f"(c[1]), "+f"(c[2]), "+f"(c[3])
        : "r"(a[0]), "r"(a[1]), "r"(a[2]), "r"(a[3]), "r"(b0), "r"(b1));
}

// ===========================================================================
// Kernel 1: khsG — blocks 0..97: hist -> device-sync -> scan -> scatter
//                  blocks 98..353: G1 segment-sum, MLP-4 (no waiting)
// Deadlock-free: all 354 CTAs are co-resident (low regs/smem).
// ===========================================================================
__global__ void __launch_bounds__(320) khsG(const int* __restrict__ cl,
                                            const float* __restrict__ W1) {
    int t = threadIdx.x, lane = t & 31, w = t >> 5;
    if (blockIdx.x >= NSC) {
        // ---- G1 = segment-sum of W1, 4 items in flight per thread ----
        if (t >= 256) return;
        int d = t & 63;
        int stripe = (blockIdx.x - NSC)*4 + (t >> 6);
        const int ns = 256*4;  // 1024 stripes
        float acc[NCL];
#pragma unroll
        for (int k = 0; k < NCL; k++) acc[k] = 0.0f;
        int i = stripe;
        for (; i + 3*ns < NIT; i += 4*ns) {
            int   c0 = cl[i],           c1 = cl[i + ns];
            int   c2 = cl[i + 2*ns],    c3 = cl[i + 3*ns];
            float w0 = W1[(size_t)i*DD + d];
            float w1 = W1[(size_t)(i + ns)*DD + d];
            float w2 = W1[(size_t)(i + 2*ns)*DD + d];
            float w3 = W1[(size_t)(i + 3*ns)*DD + d];
#pragma unroll
            for (int k = 0; k < NCL; k++) {
                if (c0 == k) acc[k] += w0;
                if (c1 == k) acc[k] += w1;
                if (c2 == k) acc[k] += w2;
                if (c3 == k) acc[k] += w3;
            }
        }
        for (; i < NIT; i += ns) {
            int c = cl[i];
            float w0 = W1[(size_t)i*DD + d];
#pragma unroll
            for (int k = 0; k < NCL; k++) if (c == k) acc[k] += w0;
        }
#pragma unroll
        for (int k = 0; k < NCL; k++) atomicAdd(&g_G1[k*DD + d], acc[k]);
        return;
    }

    int bid = blockIdx.x;
    // ---- phase 1: histogram of my span ----
    __shared__ int h[NCL];
    if (t < NCL) h[t] = 0;
    __syncthreads();
    int base = bid * SSPAN;
    if (t < 256) {
        int cnt[NCL];
#pragma unroll
        for (int k = 0; k < NCL; k++) cnt[k] = 0;
#pragma unroll
        for (int q = 0; q < 4; q++) {
            int i = base + q*256 + t;
            if (i < NIT) {
                int c = cl[i];
#pragma unroll
                for (int k = 0; k < NCL; k++) if (c == k) cnt[k]++;
            }
        }
#pragma unroll
        for (int k = 0; k < NCL; k++) if (cnt[k]) atomicAdd(&h[k], cnt[k]);
    }
    __syncthreads();
    if (t < NCL) g_hist[bid*NCL + t] = h[t];
    __threadfence();
    __syncthreads();
    if (t == 0) {
        atomicAdd(&g_c1, 1);
        while (*(volatile int*)&g_c1 != NSC) __nanosleep(64);
    }
    __syncthreads();

    // ---- phase 2: scan (warp per cluster) ----
    __shared__ int run[NCL];
    __shared__ int wc[8][NCL];
    __shared__ int tot_s[NCL], pre_s[NCL];
    if (w < NCL) {
        int c = w, full = 0, pre = 0;
        for (int b = lane; b < NSC; b += 32) {
            int v = g_hist[b*NCL + c];
            full += v;
            if (b < bid) pre += v;
        }
#pragma unroll
        for (int o = 16; o; o >>= 1) {
            full += __shfl_xor_sync(~0u, full, o);
            pre  += __shfl_xor_sync(~0u, pre,  o);
        }
        if (!lane) { tot_s[c] = full; pre_s[c] = pre; }
    }
    __syncthreads();
    if (t == 0) {
        int r = 0;
        for (int k = 0; k < NCL; k++) {
            int o = r; r += tot_s[k];
            run[k] = o + pre_s[k];
            if (bid == 0) { g_coff[k] = o; g_cntf[k] = (float)tot_s[k]; }
        }
        if (bid == 0) g_coff[NCL] = r;
    }
    __syncthreads();

    // ---- phase 3: rank + scatter ----
    unsigned ltm = (1u << lane) - 1u;
    for (int q = 0; q < 4; q++) {
        if (t < 80) ((int*)wc)[t] = 0;
        __syncthreads();
        int i = base + q*256 + t;
        int c = (t < 256 && i < NIT) ? cl[i] : -1;
        unsigned mm = __match_any_sync(0xffffffffu, c);
        int myrank = __popc(mm & ltm);
        if (c >= 0 && myrank == 0) wc[w][c] = __popc(mm);
        __syncthreads();
        if (t < NCL) {
            int k = t, s = run[k];
            for (int ww = 0; ww < 8; ww++) { int tmp = wc[ww][k]; wc[ww][k] = s; s += tmp; }
            run[k] = s;
        }
        __syncthreads();
        if (c >= 0) g_dst[i] = wc[w][c] + myrank;
        __syncthreads();
    }
}

// ===========================================================================
// Kernel 2: kperm — W2 permute/transpose/bf16 only
// ===========================================================================
#define PITCH 264
__global__ void kperm(const float* __restrict__ W2) {
    extern __shared__ unsigned short shh[];
    int t = threadIdx.x;
    int i = blockIdx.x * 256 + t;
#pragma unroll 8
    for (int d = 0; d < DD; d++) {
        float x = (i < NIT) ? W2[(size_t)d*NIT + i] : 0.0f;
        shh[d*PITCH + t] = __bfloat16_as_ushort(__float2bfloat16(x));
    }
    __syncthreads();
    if (i >= NIT) return;
    int dp = g_dst[i];
    uint v[32];
#pragma unroll
    for (int j = 0; j < 32; j++)
        v[j] = (uint)shh[(2*j)*PITCH + t] | ((uint)shh[(2*j+1)*PITCH + t] << 16);
    uint4* dh = (uint4*)(g_W2h + (size_t)dp*DD);
#pragma unroll
    for (int q = 0; q < 8; q++) dh[q] = make_uint4(v[4*q], v[4*q+1], v[4*q+2], v[4*q+3]);
}

// ===========================================================================
// Kernel 3: kmain — H prologue + bf16 HMMA (4x2 warp split) + fused finalize
// warp layout: wr = w&3 (32 rows), wi = w>>2 (64 items)
// ===========================================================================
__device__ __forceinline__ void stage_B(uint32_t sb, int buf, int ch, int t) {
    uint32_t bh = sb + SM_B0 + buf*16384;
    const char* gh = (const char*)g_W2h + (size_t)ch*CH*128;
#pragma unroll
    for (int q = 0; q < 4; q++) {
        int off = (t + q*256) * 16;
        cpa16(bh + SW128(off), gh + off);
    }
}

// MMA for one 16-item quarter: acc[4][4] = {m0n0, m0n1, m1n0, m1n1}
__device__ __forceinline__ void mma_quarter(float (*acc)[4], const uint (*ah)[4],
                                            uint32_t bq, const int* bx) {
#pragma unroll
    for (int j = 0; j < 4; j++)
#pragma unroll
        for (int k = 0; k < 4; k++) acc[j][k] = 0.0f;
#pragma unroll
    for (int ks = 0; ks < 4; ks++) {
        uint r[4];
        LDSM4(r, bq + bx[ks]);
        mma_bf16(acc[0], ah[0*4 + ks], r[0], r[1]);
        mma_bf16(acc[1], ah[0*4 + ks], r[2], r[3]);
        mma_bf16(acc[2], ah[1*4 + ks], r[0], r[1]);
        mma_bf16(acc[3], ah[1*4 + ks], r[2], r[3]);
    }
}

// exp2 + segment accumulate for one 16-item quarter
__device__ __forceinline__ void epi_quarter(const float (*acc)[4], int pq, int bpos,
                                            bool fast, float* s0, float* s1) {
    if (fast) {
        s0[0] += ex2f(acc[0][0]) + ex2f(acc[0][1]) + ex2f(acc[1][0]) + ex2f(acc[1][1]);
        s0[1] += ex2f(acc[0][2]) + ex2f(acc[0][3]) + ex2f(acc[1][2]) + ex2f(acc[1][3]);
        s0[2] += ex2f(acc[2][0]) + ex2f(acc[2][1]) + ex2f(acc[3][0]) + ex2f(acc[3][1]);
        s0[3] += ex2f(acc[2][2]) + ex2f(acc[2][3]) + ex2f(acc[3][2]) + ex2f(acc[3][3]);
    } else {
#pragma unroll
        for (int jm = 0; jm < 2; jm++)
#pragma unroll
            for (int jn = 0; jn < 2; jn++) {
                int j = jm*2 + jn;
                int p = pq + jn*8;
                float e0 = ex2f(acc[j][0]), e1 = ex2f(acc[j][1]);
                float e2 = ex2f(acc[j][2]), e3 = ex2f(acc[j][3]);
                if (p < bpos)          { s0[jm*2]   += e0; }
                else if (p < NIT)      { s1[jm*2]   += e0; }
                if (p + 1 < bpos)      { s0[jm*2]   += e1; }
                else if (p + 1 < NIT)  { s1[jm*2]   += e1; }
                if (p < bpos)          { s0[jm*2+1] += e2; }
                else if (p < NIT)      { s1[jm*2+1] += e2; }
                if (p + 1 < bpos)      { s0[jm*2+1] += e3; }
                else if (p + 1 < NIT)  { s1[jm*2+1] += e3; }
            }
    }
}

__global__ void __launch_bounds__(256, 2) kmain(const float* __restrict__ inp,
                                                float* __restrict__ out) {
    extern __shared__ char dsm[];
    __shared__ int coff_s[NCL+1];
    __shared__ int slast;
    uint32_t sb0 = smem_u32(dsm);
    uint32_t pad = (1024u - (sb0 & 1023u)) & 1023u;
    uint32_t sb  = sb0 + pad;
    char*    bp  = dsm + pad;

    int t = threadIdx.x, lane = t & 31, w = t >> 5;
    int wr = w & 3, wi = w >> 2;
    int bbase = blockIdx.x * BT;
    int ch_lo = blockIdx.y * CPS;
    int ch_hi = min(ch_lo + CPS, NCH);
    int n = ch_hi - ch_lo;

    if (t < NCL+1) coff_s[t] = g_coff[t];

    // ---- prologue: compute H tile (input @ G1)*log2e -> bf16 -> A smem ----
    {
        float* finp = (float*)(bp + SM_B0);          // 1280 f
        float* fg1  = finp + BT*NCL;                 // 640 f
        for (int idx = t; idx < BT*NCL; idx += 256) finp[idx] = inp[bbase*NCL + idx];
        for (int idx = t; idx < NCL*DD; idx += 256) fg1[idx] = g_G1[idx];
        __syncthreads();
        for (int idx = t; idx < BT*DD; idx += 256) {
            int row = idx >> 6, d = idx & 63;
            float a = 0.0f;
#pragma unroll
            for (int c = 0; c < NCL; c++) a += finp[row*NCL + c] * fg1[c*DD + d];
            a *= LOG2E;
            *(unsigned short*)(bp + SM_AH + SW128(row*128 + d*2)) =
                __bfloat16_as_ushort(__float2bfloat16(a));
        }
        __syncthreads();   // scratch consumed, A visible
    }
    stage_B(sb, 0, ch_lo, t);
    CPA_COMMIT();

    // per-lane ldmatrix B address precompute (relative to quarter base)
    int m  = lane >> 3, rl = lane & 7;
    int rowb = ((m >> 1) << 3) + rl;
    int kadd = m & 1;
    int bx[4];
#pragma unroll
    for (int ks = 0; ks < 4; ks++)
        bx[ks] = rowb*128 + ((ks*32 + kadd*16) ^ (rl*16));

    // A fragments: 2 m-tiles x 4 k-steps, resident
    uint ah[8][4];
    {
#pragma unroll
        for (int mt = 0; mt < 2; mt++) {
            int arow = wr*32 + mt*16 + ((lane >> 3) & 1)*8 + rl;
#pragma unroll
            for (int ks = 0; ks < 4; ks++) {
                int au   = ks*2 + (lane >> 4);
                LDSM4(ah[mt*4 + ks], sb + SM_AH + arow*128 + ((au*16) ^ (rl*16)));
            }
        }
    }

    int rbase = bbase + wr*32 + (lane >> 2);   // rows rbase + {0,8,16,24}
    int qd    = (lane & 3) * 2;
    float s0[4] = {0,0,0,0}, s1[4] = {0,0,0,0};
    int cur = 0;
    { int ib = ch_lo * CH; while (coff_s[cur+1] <= ib) cur++; }

    for (int ii = 0; ii < n; ii++) {
        int buf = ii & 1;
        if (ii + 1 < n) { stage_B(sb, buf ^ 1, ch_lo + ii + 1, t); CPA_COMMIT(); CPA_WAIT1(); }
        else            { CPA_WAIT0(); }
        __syncthreads();

        uint32_t bbh = sb + SM_B0 + buf*16384 + wi*4*2048;   // my 64-item half
        int ibase = (ch_lo + ii) * CH;

        // cluster-boundary flush
        {
            int nc = cur;
            while (coff_s[nc+1] <= ibase) nc++;
            if (nc != cur) {
#pragma unroll
                for (int sl = 0; sl < 4; sl++) {
                    atomicAdd(&g_sums[(rbase + sl*8)*NCL + cur], s0[sl]);
                    if (cur + 1 < NCL) atomicAdd(&g_sums[(rbase + sl*8)*NCL + cur + 1], s1[sl]);
                    s0[sl] = 0.f; s1[sl] = 0.f;
                }
                cur = nc;
            }
        }
        int bpos = coff_s[cur+1];
        bool fast = (ibase + CH <= bpos);
        int pq0 = ibase + wi*64 + qd;

        // quarter-pipelined (16 items each): MMA(q) overlaps EPI(q-1)
        float accA[4][4], accB[4][4];
        mma_quarter(accA, (const uint(*)[4])ah, bbh + 0*2048, bx);
        mma_quarter(accB, (const uint(*)[4])ah, bbh + 1*2048, bx);
        epi_quarter(accA, pq0,      bpos, fast, s0, s1);
        mma_quarter(accA, (const uint(*)[4])ah, bbh + 2*2048, bx);
        epi_quarter(accB, pq0 + 16, bpos, fast, s0, s1);
        mma_quarter(accB, (const uint(*)[4])ah, bbh + 3*2048, bx);
        epi_quarter(accA, pq0 + 32, bpos, fast, s0, s1);
        epi_quarter(accB, pq0 + 48, bpos, fast, s0, s1);

        __syncthreads();
    }

#pragma unroll
    for (int sl = 0; sl < 4; sl++) {
        atomicAdd(&g_sums[(rbase + sl*8)*NCL + cur], s0[sl]);
        if (cur + 1 < NCL) atomicAdd(&g_sums[(rbase + sl*8)*NCL + cur + 1], s1[sl]);
    }

    // ---- fused finalize: last CTA computes output + restores zeros ----
    __threadfence();
    __syncthreads();
    if (t == 0) slast = (atomicAdd(&g_c2, 1) == (int)(gridDim.x*gridDim.y) - 1);
    __syncthreads();
    if (slast) {
        __threadfence();
        for (int b = t; b < NB; b += 256) {
            float v[NCL], z = 0.0f;
#pragma unroll
            for (int c = 0; c < NCL; c++) { v[c] = g_sums[b*NCL + c]; z += v[c]; }
            float invz = 1.0f / z;
#pragma unroll
            for (int c = 0; c < NCL; c++)
                out[b*NCL + c] = v[c] * invz / fmaxf(g_cntf[c], 1.0f);
#pragma unroll
            for (int c = 0; c < NCL; c++) g_sums[b*NCL + c] = 0.0f;
        }
        for (int i = t; i < NCL*DD; i += 256) g_G1[i] = 0.0f;
        if (t == 0) { g_c1 = 0; g_c2 = 0; }
    }
}

// ---------------------------------------------------------------------------
extern "C" void kernel_launch(void* const* d_in, const int* in_sizes, int n_in,
                              void* d_out, int out_size) {
    const float* input = (const float*)d_in[0];   // (1024, 10) f32
    const int*   clust = (const int*)d_in[1];     // (100000,) i32
    const float* W1    = (const float*)d_in[2];   // (100000, 64) f32
    const float* W2    = (const float*)d_in[3];   // (64, 100000) f32
    float*       out   = (float*)d_out;           // (1024, 10) f32

    cudaFuncSetAttribute(kmain, cudaFuncAttributeMaxDynamicSharedMemorySize, SMEM_KM);
    cudaFuncSetAttribute(kperm, cudaFuncAttributeMaxDynamicSharedMemorySize, DD*PITCH*2);

    khsG<<<NSC + 256, 320>>>(clust, W1);
    kperm<<<391, 256, DD*PITCH*2>>>(W2);
    dim3 grid(NB / BT, NS);
    kmain<<<grid, 256, SMEM_KM>>>(input, out);
}

// round 11
// speedup vs baseline: 1.1769x; 1.0263x over previous
#include <cuda_runtime.h>
#include <cuda_bf16.h>
#include <cstdint>

typedef unsigned int uint;

#define NB      1024
#define NIT     100000
#define NCL     10
#define DD      64
#define CH      128                  // items per chunk
#define NCH     782                  // NP / CH
#define NP      (NCH*CH)             // 100096
#define NS      36                   // item splits (contiguous ranges)
#define CPS     22                   // chunks per CTA
#define BT      128                  // batch rows per CTA
#define NSC     98                   // sort/scatter blocks
#define GB      256                  // G1 blocks
#define PB      391                  // perm blocks
#define SSPAN   1024
#define LOG2E   1.4426950408889634f
#define PITCH   264

// kmain smem (relative to 1024-aligned base): Ah@0 (16K) | B0@16K B1@32K
#define SM_AH   0
#define SM_B0   16384
#define SMEM_KM (49152 + 1024)
#define SMEM_KP (DD*PITCH*2)         // 33792 B, perm staging

// ---------------- device scratch (zero at load; kmain-fin restores) --------
__device__ float  g_G1[NCL*DD];
__device__ float  g_sums[NB*NCL];
__device__ float  g_cntf[NCL];
__device__ int    g_hist[NSC*NCL];
__device__ int    g_coff[NCL+1];
__device__ int    g_dst[NIT];
__device__ int    g_c1;              // hist-done counter
__device__ int    g_c2;              // kmain-done counter
__device__ int    g_c3;              // scatter-done counter
__device__ __align__(16) unsigned short g_W2h[(size_t)NP*DD];   // padding rows stay 0 forever

// ---------------- PTX helpers (sm_80-class baseline ISA) --------------------
__device__ __forceinline__ uint32_t smem_u32(const void* p) {
    uint32_t a;
    asm("{ .reg .u64 t; cvta.to.shared.u64 t, %1; cvt.u32.u64 %0, t; }" : "=r"(a) : "l"(p));
    return a;
}
__device__ __forceinline__ float ex2f(float x) {
    float r; asm("ex2.approx.ftz.f32 %0, %1;" : "=f"(r) : "f"(x)); return r;
}
#define SW128(o) ((o) ^ (((o) >> 3) & 0x70))

__device__ __forceinline__ void cpa16(uint32_t dst, const void* src) {
    asm volatile("cp.async.cg.shared.global [%0], [%1], 16;" :: "r"(dst), "l"(src));
}
#define CPA_COMMIT() asm volatile("cp.async.commit_group;")
#define CPA_WAIT0()  asm volatile("cp.async.wait_group 0;" ::: "memory")
#define CPA_WAIT1()  asm volatile("cp.async.wait_group 1;" ::: "memory")

#define LDSM4(R, A) \
    asm volatile("ldmatrix.sync.aligned.m8n8.x4.shared.b16 {%0,%1,%2,%3}, [%4];" \
        : "=r"((R)[0]), "=r"((R)[1]), "=r"((R)[2]), "=r"((R)[3]) : "r"(A))

__device__ __forceinline__ void mma_bf16(float* c, const uint* a, uint b0, uint b1) {
    asm volatile("mma.sync.aligned.m16n8k16.row.col.f32.bf16.bf16.f32 "
        "{%0,%1,%2,%3}, {%4,%5,%6,%7}, {%8,%9}, {%0,%1,%2,%3};"
        : "+f"(c[0]), "+f"(c[1]), "+f"(c[2]), "+f"(c[3])
        : "r"(a[0]), "r"(a[1]), "r"(a[2]), "r"(a[3]), "r"(b0), "r"(b1));
}

// ===========================================================================
// Kernel 1: kprep — one launch, three block ranges:
//   0..97          : hist -> sync(g_c1) -> scan -> scatter -> signal g_c3
//   98..353        : G1 segment-sum, MLP-16 (no waiting)
//   354..744       : W2 permute, spin on g_c3 == NSC first
// Deadlock-free: signaler blocks (0..97) are lowest-index -> wave-1 resident.
// ===========================================================================
__global__ void __launch_bounds__(320) kprep(const int* __restrict__ cl,
                                             const float* __restrict__ W1,
                                             const float* __restrict__ W2) {
    int t = threadIdx.x, lane = t & 31, w = t >> 5;
    int bid = blockIdx.x;

    if (bid >= NSC + GB) {
        // ================= perm phase =================
        if (t >= 256) return;
        __shared__ int ok;
        if (t == 0) {
            while (*(volatile int*)&g_c3 != NSC) __nanosleep(128);
            ok = 1;
        }
        __syncthreads();
        (void)ok;
        __threadfence();   // acquire: g_dst visible
        extern __shared__ unsigned short shh[];
        int pid = bid - (NSC + GB);
        int i = pid * 256 + t;
#pragma unroll 8
        for (int d = 0; d < DD; d++) {
            float x = (i < NIT) ? W2[(size_t)d*NIT + i] : 0.0f;
            shh[d*PITCH + t] = __bfloat16_as_ushort(__float2bfloat16(x));
        }
        __syncthreads();
        if (i >= NIT) return;
        int dp = g_dst[i];
        uint v[32];
#pragma unroll
        for (int j = 0; j < 32; j++)
            v[j] = (uint)shh[(2*j)*PITCH + t] | ((uint)shh[(2*j+1)*PITCH + t] << 16);
        uint4* dh = (uint4*)(g_W2h + (size_t)dp*DD);
#pragma unroll
        for (int q = 0; q < 8; q++) dh[q] = make_uint4(v[4*q], v[4*q+1], v[4*q+2], v[4*q+3]);
        return;
    }

    if (bid >= NSC) {
        // ================= G1 phase: 16 items in flight per thread ========
        if (t >= 256) return;
        int d = t & 63;
        int stripe = (bid - NSC)*4 + (t >> 6);
        const int ns = GB*4;   // 1024 stripes
        float acc[NCL];
#pragma unroll
        for (int k = 0; k < NCL; k++) acc[k] = 0.0f;
        int i = stripe;
        for (; i + 15*ns < NIT; i += 16*ns) {
            int cc[16]; float wv[16];
#pragma unroll
            for (int j = 0; j < 16; j++) cc[j] = cl[i + j*ns];
#pragma unroll
            for (int j = 0; j < 16; j++) wv[j] = W1[(size_t)(i + j*ns)*DD + d];
#pragma unroll
            for (int k = 0; k < NCL; k++) {
#pragma unroll
                for (int j = 0; j < 16; j++) if (cc[j] == k) acc[k] += wv[j];
            }
        }
        for (; i < NIT; i += ns) {
            int c = cl[i];
            float w0 = W1[(size_t)i*DD + d];
#pragma unroll
            for (int k = 0; k < NCL; k++) if (c == k) acc[k] += w0;
        }
#pragma unroll
        for (int k = 0; k < NCL; k++) atomicAdd(&g_G1[k*DD + d], acc[k]);
        return;
    }

    // ================= hist -> scan -> scatter =================
    __shared__ int h[NCL];
    if (t < NCL) h[t] = 0;
    __syncthreads();
    int base = bid * SSPAN;
    if (t < 256) {
        int cnt[NCL];
#pragma unroll
        for (int k = 0; k < NCL; k++) cnt[k] = 0;
#pragma unroll
        for (int q = 0; q < 4; q++) {
            int i = base + q*256 + t;
            if (i < NIT) {
                int c = cl[i];
#pragma unroll
                for (int k = 0; k < NCL; k++) if (c == k) cnt[k]++;
            }
        }
#pragma unroll
        for (int k = 0; k < NCL; k++) if (cnt[k]) atomicAdd(&h[k], cnt[k]);
    }
    __syncthreads();
    if (t < NCL) g_hist[bid*NCL + t] = h[t];
    __threadfence();
    __syncthreads();
    if (t == 0) {
        atomicAdd(&g_c1, 1);
        while (*(volatile int*)&g_c1 != NSC) __nanosleep(64);
    }
    __syncthreads();

    __shared__ int run[NCL];
    __shared__ int wc[8][NCL];
    __shared__ int tot_s[NCL], pre_s[NCL];
    if (w < NCL) {
        int c = w, full = 0, pre = 0;
        for (int b = lane; b < NSC; b += 32) {
            int v = g_hist[b*NCL + c];
            full += v;
            if (b < bid) pre += v;
        }
#pragma unroll
        for (int o = 16; o; o >>= 1) {
            full += __shfl_xor_sync(~0u, full, o);
            pre  += __shfl_xor_sync(~0u, pre,  o);
        }
        if (!lane) { tot_s[c] = full; pre_s[c] = pre; }
    }
    __syncthreads();
    if (t == 0) {
        int r = 0;
        for (int k = 0; k < NCL; k++) {
            int o = r; r += tot_s[k];
            run[k] = o + pre_s[k];
            if (bid == 0) { g_coff[k] = o; g_cntf[k] = (float)tot_s[k]; }
        }
        if (bid == 0) g_coff[NCL] = r;
    }
    __syncthreads();

    unsigned ltm = (1u << lane) - 1u;
    for (int q = 0; q < 4; q++) {
        if (t < 80) ((int*)wc)[t] = 0;
        __syncthreads();
        int i = base + q*256 + t;
        int c = (t < 256 && i < NIT) ? cl[i] : -1;
        unsigned mm = __match_any_sync(0xffffffffu, c);
        int myrank = __popc(mm & ltm);
        if (c >= 0 && myrank == 0) wc[w][c] = __popc(mm);
        __syncthreads();
        if (t < NCL) {
            int k = t, s = run[k];
            for (int ww = 0; ww < 8; ww++) { int tmp = wc[ww][k]; wc[ww][k] = s; s += tmp; }
            run[k] = s;
        }
        __syncthreads();
        if (c >= 0) g_dst[i] = wc[w][c] + myrank;
        __syncthreads();
    }
    // signal scatter-done (release)
    __threadfence();
    __syncthreads();
    if (t == 0) atomicAdd(&g_c3, 1);
}

// ===========================================================================
// Kernel 2: kmain — H prologue + bf16 HMMA (4x2 warp split) + fused finalize
// ===========================================================================
__device__ __forceinline__ void stage_B(uint32_t sb, int buf, int ch, int t) {
    uint32_t bh = sb + SM_B0 + buf*16384;
    const char* gh = (const char*)g_W2h + (size_t)ch*CH*128;
#pragma unroll
    for (int q = 0; q < 4; q++) {
        int off = (t + q*256) * 16;
        cpa16(bh + SW128(off), gh + off);
    }
}

__device__ __forceinline__ void mma_quarter(float (*acc)[4], const uint (*ah)[4],
                                            uint32_t bq, const int* bx) {
#pragma unroll
    for (int j = 0; j < 4; j++)
#pragma unroll
        for (int k = 0; k < 4; k++) acc[j][k] = 0.0f;
#pragma unroll
    for (int ks = 0; ks < 4; ks++) {
        uint r[4];
        LDSM4(r, bq + bx[ks]);
        mma_bf16(acc[0], ah[0*4 + ks], r[0], r[1]);
        mma_bf16(acc[1], ah[0*4 + ks], r[2], r[3]);
        mma_bf16(acc[2], ah[1*4 + ks], r[0], r[1]);
        mma_bf16(acc[3], ah[1*4 + ks], r[2], r[3]);
    }
}

__device__ __forceinline__ void epi_quarter(const float (*acc)[4], int pq, int bpos,
                                            bool fast, float* s0, float* s1) {
    if (fast) {
        s0[0] += ex2f(acc[0][0]) + ex2f(acc[0][1]) + ex2f(acc[1][0]) + ex2f(acc[1][1]);
        s0[1] += ex2f(acc[0][2]) + ex2f(acc[0][3]) + ex2f(acc[1][2]) + ex2f(acc[1][3]);
        s0[2] += ex2f(acc[2][0]) + ex2f(acc[2][1]) + ex2f(acc[3][0]) + ex2f(acc[3][1]);
        s0[3] += ex2f(acc[2][2]) + ex2f(acc[2][3]) + ex2f(acc[3][2]) + ex2f(acc[3][3]);
    } else {
#pragma unroll
        for (int jm = 0; jm < 2; jm++)
#pragma unroll
            for (int jn = 0; jn < 2; jn++) {
                int j = jm*2 + jn;
                int p = pq + jn*8;
                float e0 = ex2f(acc[j][0]), e1 = ex2f(acc[j][1]);
                float e2 = ex2f(acc[j][2]), e3 = ex2f(acc[j][3]);
                if (p < bpos)          { s0[jm*2]   += e0; }
                else if (p < NIT)      { s1[jm*2]   += e0; }
                if (p + 1 < bpos)      { s0[jm*2]   += e1; }
                else if (p + 1 < NIT)  { s1[jm*2]   += e1; }
                if (p < bpos)          { s0[jm*2+1] += e2; }
                else if (p < NIT)      { s1[jm*2+1] += e2; }
                if (p + 1 < bpos)      { s0[jm*2+1] += e3; }
                else if (p + 1 < NIT)  { s1[jm*2+1] += e3; }
            }
    }
}

__global__ void __launch_bounds__(256, 2) kmain(const float* __restrict__ inp,
                                                float* __restrict__ out) {
    extern __shared__ char dsm[];
    __shared__ int coff_s[NCL+1];
    __shared__ int slast;
    uint32_t sb0 = smem_u32(dsm);
    uint32_t pad = (1024u - (sb0 & 1023u)) & 1023u;
    uint32_t sb  = sb0 + pad;
    char*    bp  = dsm + pad;

    int t = threadIdx.x, lane = t & 31, w = t >> 5;
    int wr = w & 3, wi = w >> 2;
    int bbase = blockIdx.x * BT;
    int ch_lo = blockIdx.y * CPS;
    int ch_hi = min(ch_lo + CPS, NCH);
    int n = ch_hi - ch_lo;

    if (t < NCL+1) coff_s[t] = g_coff[t];

    // ---- prologue: compute H tile (input @ G1)*log2e -> bf16 -> A smem ----
    {
        float* finp = (float*)(bp + SM_B0);
        float* fg1  = finp + BT*NCL;
        for (int idx = t; idx < BT*NCL; idx += 256) finp[idx] = inp[bbase*NCL + idx];
        for (int idx = t; idx < NCL*DD; idx += 256) fg1[idx] = g_G1[idx];
        __syncthreads();
        for (int idx = t; idx < BT*DD; idx += 256) {
            int row = idx >> 6, d = idx & 63;
            float a = 0.0f;
#pragma unroll
            for (int c = 0; c < NCL; c++) a += finp[row*NCL + c] * fg1[c*DD + d];
            a *= LOG2E;
            *(unsigned short*)(bp + SM_AH + SW128(row*128 + d*2)) =
                __bfloat16_as_ushort(__float2bfloat16(a));
        }
        __syncthreads();
    }
    stage_B(sb, 0, ch_lo, t);
    CPA_COMMIT();

    int m  = lane >> 3, rl = lane & 7;
    int rowb = ((m >> 1) << 3) + rl;
    int kadd = m & 1;
    int bx[4];
#pragma unroll
    for (int ks = 0; ks < 4; ks++)
        bx[ks] = rowb*128 + ((ks*32 + kadd*16) ^ (rl*16));

    uint ah[8][4];
    {
#pragma unroll
        for (int mt = 0; mt < 2; mt++) {
            int arow = wr*32 + mt*16 + ((lane >> 3) & 1)*8 + rl;
#pragma unroll
            for (int ks = 0; ks < 4; ks++) {
                int au   = ks*2 + (lane >> 4);
                LDSM4(ah[mt*4 + ks], sb + SM_AH + arow*128 + ((au*16) ^ (rl*16)));
            }
        }
    }

    int rbase = bbase + wr*32 + (lane >> 2);
    int qd    = (lane & 3) * 2;
    float s0[4] = {0,0,0,0}, s1[4] = {0,0,0,0};
    int cur = 0;
    { int ib = ch_lo * CH; while (coff_s[cur+1] <= ib) cur++; }

    for (int ii = 0; ii < n; ii++) {
        int buf = ii & 1;
        if (ii + 1 < n) { stage_B(sb, buf ^ 1, ch_lo + ii + 1, t); CPA_COMMIT(); CPA_WAIT1(); }
        else            { CPA_WAIT0(); }
        __syncthreads();

        uint32_t bbh = sb + SM_B0 + buf*16384 + wi*4*2048;
        int ibase = (ch_lo + ii) * CH;

        {
            int nc = cur;
            while (coff_s[nc+1] <= ibase) nc++;
            if (nc != cur) {
#pragma unroll
                for (int sl = 0; sl < 4; sl++) {
                    atomicAdd(&g_sums[(rbase + sl*8)*NCL + cur], s0[sl]);
                    if (cur + 1 < NCL) atomicAdd(&g_sums[(rbase + sl*8)*NCL + cur + 1], s1[sl]);
                    s0[sl] = 0.f; s1[sl] = 0.f;
                }
                cur = nc;
            }
        }
        int bpos = coff_s[cur+1];
        bool fast = (ibase + CH <= bpos);
        int pq0 = ibase + wi*64 + qd;

        float accA[4][4], accB[4][4];
        mma_quarter(accA, (const uint(*)[4])ah, bbh + 0*2048, bx);
        mma_quarter(accB, (const uint(*)[4])ah, bbh + 1*2048, bx);
        epi_quarter(accA, pq0,      bpos, fast, s0, s1);
        mma_quarter(accA, (const uint(*)[4])ah, bbh + 2*2048, bx);
        epi_quarter(accB, pq0 + 16, bpos, fast, s0, s1);
        mma_quarter(accB, (const uint(*)[4])ah, bbh + 3*2048, bx);
        epi_quarter(accA, pq0 + 32, bpos, fast, s0, s1);
        epi_quarter(accB, pq0 + 48, bpos, fast, s0, s1);

        __syncthreads();
    }

#pragma unroll
    for (int sl = 0; sl < 4; sl++) {
        atomicAdd(&g_sums[(rbase + sl*8)*NCL + cur], s0[sl]);
        if (cur + 1 < NCL) atomicAdd(&g_sums[(rbase + sl*8)*NCL + cur + 1], s1[sl]);
    }

    // ---- fused finalize: last CTA computes output + restores scratch -----
    __threadfence();
    __syncthreads();
    if (t == 0) slast = (atomicAdd(&g_c2, 1) == (int)(gridDim.x*gridDim.y) - 1);
    __syncthreads();
    if (slast) {
        __threadfence();
        for (int b = t; b < NB; b += 256) {
            float v[NCL], z = 0.0f;
#pragma unroll
            for (int c = 0; c < NCL; c++) { v[c] = g_sums[b*NCL + c]; z += v[c]; }
            float invz = 1.0f / z;
#pragma unroll
            for (int c = 0; c < NCL; c++)
                out[b*NCL + c] = v[c] * invz / fmaxf(g_cntf[c], 1.0f);
#pragma unroll
            for (int c = 0; c < NCL; c++) g_sums[b*NCL + c] = 0.0f;
        }
        for (int i = t; i < NCL*DD; i += 256) g_G1[i] = 0.0f;
        if (t == 0) { g_c1 = 0; g_c2 = 0; g_c3 = 0; }
    }
}

// ---------------------------------------------------------------------------
extern "C" void kernel_launch(void* const* d_in, const int* in_sizes, int n_in,
                              void* d_out, int out_size) {
    const float* input = (const float*)d_in[0];   // (1024, 10) f32
    const int*   clust = (const int*)d_in[1];     // (100000,) i32
    const float* W1    = (const float*)d_in[2];   // (100000, 64) f32
    const float* W2    = (const float*)d_in[3];   // (64, 100000) f32
    float*       out   = (float*)d_out;           // (1024, 10) f32

    cudaFuncSetAttribute(kmain, cudaFuncAttributeMaxDynamicSharedMemorySize, SMEM_KM);
    cudaFuncSetAttribute(kprep, cudaFuncAttributeMaxDynamicSharedMemorySize, SMEM_KP);

    kprep<<<NSC + GB + PB, 320, SMEM_KP>>>(clust, W1, W2);
    dim3 grid(NB / BT, NS);
    kmain<<<grid, 256, SMEM_KM>>>(input, out);
}